// round 17
// baseline (speedup 1.0000x reference)
#include <cuda_runtime.h>
#include <cuda_fp16.h>
#include <cstdint>
#include <math.h>

// Problem constants: B=8, C=128, T=128, F=512, K=64
static constexpr int SL = 8192;    // latent positions/batch
static constexpr int SS = 65536;   // side positions/batch

// ---------------- scratch (device globals; no cudaMalloc allowed) ----------
__device__ float g_kbuf[8 * 128 * 8192];
__device__ float g_vbuf[8 * 128 * 8192];
__device__ float g_qh[(size_t)8 * 128 * 65536];
__device__ float g_q[(size_t)8 * 128 * 65536];
// fp16 pre-swizzled tile tensors: 32KB tiles of [128 k][128 m]
__device__ uint4 g_lat16[(size_t)8 * 64 * 2048];
__device__ uint4 g_A16[(size_t)8 * 512 * 2048];      // GLU'd swiglu hidden (both MLPs)
__device__ uint4 g_att16[(size_t)8 * 512 * 2048];
// fp16 weight fragments (A-operand layout for mma.m16n8k16)
__device__ uint4 g_Wp[704 * 32];
// composite q-weight (q_w @ qmlp_out_w) fp32 + folded bias
__device__ float g_Wc[128 * 128];
__device__ float g_bc[128];

// =================== helpers ===================
__device__ __forceinline__ uint32_t smem_u32(const void* p) {
    uint32_t a;
    asm("{ .reg .u64 t; cvta.to.shared.u64 t, %1; cvt.u32.u64 %0, t; }"
        : "=r"(a) : "l"(p));
    return a;
}
__device__ __forceinline__ unsigned pack_h2(float a, float b) {
    __half2 h = __floats2half2_rn(a, b);
    return *(unsigned*)&h;
}
// FFMA-only exp: 2^round(t) * P(frac), rel err ~2.4e-6
__device__ __forceinline__ float fast_exp(float x)
{
    x = fminf(fmaxf(x, -87.f), 88.f);
    float t = x * 1.4426950408889634f;
    float z = t + 12582912.f;
    int   i = __float_as_int(z) - 0x4B400000;
    float f = t - (z - 12582912.f);
    float p =             1.33335581e-3f;
    p = fmaf(p, f, 9.61812911e-3f);
    p = fmaf(p, f, 5.55041087e-2f);
    p = fmaf(p, f, 2.40226507e-1f);
    p = fmaf(p, f, 6.93147181e-1f);
    p = fmaf(p, f, 1.0f);
    return __int_as_float(__float_as_int(p) + (i << 23));
}
__device__ __forceinline__ float fast_rcp(float d)
{
    float r = __int_as_float(0x7EF311C3 - __float_as_int(d));
    r = r * (2.f - d * r);
    r = r * (2.f - d * r);
    return r;
}
__device__ __forceinline__ float silu(float g) {
    return g * fast_rcp(1.f + fast_exp(-g));
}
// byte offset inside a 32KB [128k][128m] fp16 tile (256B rows, XOR-swizzled)
__device__ __forceinline__ unsigned sw_off(int k, int mp) {
    return (unsigned)k * 256u + (((unsigned)mp * 2u) ^ (((unsigned)k & 7u) << 4));
}

#define MMA_F16(dd, aa, bb)                                                    \
    asm volatile("mma.sync.aligned.m16n8k16.row.col.f32.f16.f16.f32 "          \
        "{%0,%1,%2,%3}, {%4,%5,%6,%7}, {%8,%9}, {%0,%1,%2,%3};"                \
        : "+f"((dd)[0]), "+f"((dd)[1]), "+f"((dd)[2]), "+f"((dd)[3])           \
        : "r"((aa).x), "r"((aa).y), "r"((aa).z), "r"((aa).w),                  \
          "r"((bb)[0]), "r"((bb)[1]))

#define LDMX4T(b0, b1, b2, b3, addr)                                           \
    asm volatile("ldmatrix.sync.aligned.m8n8.x4.trans.shared.b16 "             \
        "{%0,%1,%2,%3}, [%4];"                                                 \
        : "=r"(b0), "=r"(b1), "=r"(b2), "=r"(b3) : "r"(addr))

// ---------------- composite weight: Wc = q_w @ qmlp_out_w ------------------
__global__ void __launch_bounds__(256) compose_w(
    const float* __restrict__ qw, const float* __restrict__ mow,
    const float* __restrict__ mob, const float* __restrict__ qb,
    float* __restrict__ Wc, float* __restrict__ bc)
{
    if (blockIdx.x == 64) {
        int o = threadIdx.x;
        if (o < 128) {
            float s = qb[o];
            for (int j = 0; j < 128; j++) s = fmaf(qw[o * 128 + j], mob[j], s);
            bc[o] = s;
        }
        return;
    }
    int idx = blockIdx.x * 256 + threadIdx.x;
    int o = idx >> 7, c = idx & 127;
    float s = 0.f;
    for (int j = 0; j < 128; j++) s = fmaf(qw[o * 128 + j], mow[j * 128 + c], s);
    Wc[idx] = s;
}

// ---------------- single weight-prep kernel (all 9 matrices) ---------------
struct WPtrs { const float* p[9]; };
__constant__ int c_tile_start[10] = {0, 64, 192, 256, 320, 384, 448, 512, 640, 704};

__global__ void __launch_bounds__(256) prep_all(WPtrs wp, uint4* __restrict__ dst)
{
    int gw = (blockIdx.x * 256 + threadIdx.x) >> 5;
    if (gw >= 704) return;
    int mi = 0;
    while (gw >= c_tile_start[mi + 1]) mi++;
    int tile = gw - c_tile_start[mi];
    const float* W = wp.p[mi];
    const int mt = tile >> 3, ks = tile & 7;
    const int l = threadIdx.x & 31;
    const int o = mt * 16 + (l >> 2);
    const int c = ks * 16 + (l & 3) * 2;
    const float* w0 = W + o * 128 + c;
    const float* w1 = W + (o + 8) * 128 + c;
    uint4 H;
    H.x = pack_h2(w0[0], w0[1]);
    H.y = pack_h2(w1[0], w1[1]);
    H.z = pack_h2(w0[8], w0[9]);
    H.w = pack_h2(w1[8], w1[9]);
    dst[gw * 32 + l] = H;
}

// =================== G1: fp32+RMSNorm input GEMM -> fp16sw output ==========
// fp32 tile staged in smem ONCE; rms + fp16 convert both read smem.
template<int NOUT>
__global__ void __launch_bounds__(256, 2) gemm_f32in(
    const uint4* __restrict__ Wp, const float* __restrict__ bias,
    const float* __restrict__ X, const float* __restrict__ gamma,
    uint4* __restrict__ Y16, int S)
{
    constexpr int MT   = (NOUT == 128) ? 128 : 64;
    constexpr int ROWB = MT * 2;
    constexpr int PAD  = MT + 4;           // fp32 row floats (padded)
    constexpr int XFB  = 128 * PAD * 4;    // fp32 tile bytes
    constexpr int ISUB = NOUT / 64;
    constexpr int WARP_M = MT / 2;
    constexpr int JQ  = WARP_M / 16;
    constexpr int JS  = WARP_M / 8;
    constexpr int TPP = 256 / MT;

    extern __shared__ __align__(16) unsigned char dynsm[];
    float* xf = (float*)dynsm;
    unsigned char* xh = dynsm + XFB;
    __shared__ float red[256];
    __shared__ float rmss[128];

    const int tid = threadIdx.x;
    const int b = blockIdx.z;
    const int m0 = blockIdx.x * MT;
    const float* Xb = X + (size_t)b * 128 * S;

    // ---- stage fp32 tile: [128 c][MT m] ----
    for (int u = tid; u < 128 * MT / 4; u += 256) {
        int c = u / (MT / 4), ms = u % (MT / 4);
        float4 v = *(const float4*)(Xb + (size_t)c * S + m0 + ms * 4);
        *(float4*)(xf + c * PAD + ms * 4) = v;
    }
    __syncthreads();

    // ---- RMS over channel dim (from smem) ----
    {
        int p = tid % MT, qd = tid / MT;
        float s = 0.f;
        for (int c = qd; c < 128; c += TPP) { float v = xf[c * PAD + p]; s = fmaf(v, v, s); }
        red[tid] = s;
        __syncthreads();
        if (tid < MT) {
            float t = 0.f;
#pragma unroll
            for (int e = 0; e < TPP; e++) t += red[tid + e * MT];
            rmss[tid] = rsqrtf(t * (1.f / 128.f) + 1e-6f);
        }
        __syncthreads();
    }

    // ---- convert smem fp32 -> smem fp16 (swizzled) ----
    for (int u = tid; u < 128 * MT / 2; u += 256) {
        int k = u / (MT / 2), j = u % (MT / 2);
        float2 v = *(const float2*)(xf + k * PAD + 2 * j);
        float gm = __ldg(gamma + k);
        v.x *= rmss[2 * j] * gm;
        v.y *= rmss[2 * j + 1] * gm;
        unsigned off = (unsigned)k * ROWB
                     + (((unsigned)(j * 4)) ^ (((unsigned)k & 7u) << 4));
        *(unsigned*)(xh + off) = pack_h2(v.x, v.y);
    }
    __syncthreads();

    // ---- mainloop ----
    const int w = tid >> 5, l = tid & 31;
    const int wm = w & 3, wn = w >> 2;
    const int mi = l >> 3, r = l & 7;
    const int k_off = (mi & 1) * 8 + r;
    const int n_off = (mi >> 1) * 8;
    const unsigned mask = ((unsigned)k_off & 7u) << 4;
    const uint32_t xrow = smem_u32(xh) + (unsigned)k_off * ROWB;

    float d[ISUB][JS][4];
#pragma unroll
    for (int i = 0; i < ISUB; i++)
#pragma unroll
        for (int j = 0; j < JS; j++)
#pragma unroll
            for (int e = 0; e < 4; e++) d[i][j][e] = 0.f;

#pragma unroll
    for (int ks = 0; ks < 8; ks++) {
        uint4 Ah[ISUB];
#pragma unroll
        for (int i = 0; i < ISUB; i++) {
            int mt = (NOUT == 256 && i >= 2) ? (8 + wm * 2 + (i - 2)) : (wm * 2 + i);
            Ah[i] = Wp[(mt * 8 + ks) * 32 + l];
        }
        unsigned bh[JS][2];
#pragma unroll
        for (int jp = 0; jp < JQ; jp++) {
            unsigned col = (unsigned)(wn * WARP_M + jp * 16 + n_off);
            unsigned r0, r1, r2, r3;
            LDMX4T(r0, r1, r2, r3, xrow + (unsigned)ks * 16u * ROWB + ((col * 2u) ^ mask));
            bh[2 * jp][0] = r0; bh[2 * jp][1] = r1;
            bh[2 * jp + 1][0] = r2; bh[2 * jp + 1][1] = r3;
        }
#pragma unroll
        for (int i = 0; i < ISUB; i++)
#pragma unroll
            for (int j = 0; j < JS; j++)
                MMA_F16(d[i][j], Ah[i], bh[j]);
    }

    // ---- epilogue -> fp16sw tile ----
    const int MTILES = S >> 7;
    unsigned char* tb = (unsigned char*)(Y16 + (size_t)(b * MTILES + (m0 >> 7)) * 2048);
    const int mpb = m0 & 127;
#pragma unroll
    for (int i = 0; i < 2; i++) {
        int k0 = wm * 32 + i * 16 + (l >> 2);
        if (NOUT == 128) {
            float b0 = __ldg(bias + k0), b1 = __ldg(bias + k0 + 8);
#pragma unroll
            for (int j = 0; j < JS; j++) {
                int m = mpb + wn * WARP_M + j * 8 + (l & 3) * 2;
                float y0 = silu(d[i][j][0] + b0), y1 = silu(d[i][j][1] + b0);
                float y2 = silu(d[i][j][2] + b1), y3 = silu(d[i][j][3] + b1);
                *(unsigned*)(tb + sw_off(k0, m))     = pack_h2(y0, y1);
                *(unsigned*)(tb + sw_off(k0 + 8, m)) = pack_h2(y2, y3);
            }
        } else {
            float ba0 = __ldg(bias + k0), ba1 = __ldg(bias + k0 + 8);
            float bg0 = __ldg(bias + 128 + k0), bg1 = __ldg(bias + 128 + k0 + 8);
#pragma unroll
            for (int j = 0; j < JS; j++) {
                int m = mpb + wn * WARP_M + j * 8 + (l & 3) * 2;
                float y0 = (d[i][j][0] + ba0) * silu(d[i + 2][j][0] + bg0);
                float y1 = (d[i][j][1] + ba0) * silu(d[i + 2][j][1] + bg0);
                float y2 = (d[i][j][2] + ba1) * silu(d[i + 2][j][2] + bg1);
                float y3 = (d[i][j][3] + ba1) * silu(d[i + 2][j][3] + bg1);
                *(unsigned*)(tb + sw_off(k0, m))     = pack_h2(y0, y1);
                *(unsigned*)(tb + sw_off(k0 + 8, m)) = pack_h2(y2, y3);
            }
        }
    }
}

// =================== G2: fp16sw input GEMM (cp.async tile copy) ============
// OUTMODE 0: fp32   2: fp32 + scale*add
template<int OUTMODE>
__global__ void __launch_bounds__(256, 2) gemm_h16(
    const uint4* __restrict__ Wp, const float* __restrict__ bias,
    const uint4* __restrict__ X16, int MTILES,
    float* __restrict__ Y,
    const float* __restrict__ addp, const float* __restrict__ addScaleP,
    int S)
{
    __shared__ __align__(16) unsigned char xh[32768];
    const int tid = threadIdx.x;
    const int b = blockIdx.z;
    const int m0 = blockIdx.x * 128;

    const uint4* gsrc = X16 + (size_t)(b * MTILES + blockIdx.x) * 2048;
    uint32_t sb = smem_u32(xh);
#pragma unroll
    for (int e = 0; e < 8; e++) {
        int idx = e * 256 + tid;
        asm volatile("cp.async.cg.shared.global [%0], [%1], 16;"
                     :: "r"(sb + idx * 16), "l"(gsrc + idx));
    }
    asm volatile("cp.async.commit_group;" ::: "memory");
    asm volatile("cp.async.wait_group 0;" ::: "memory");
    __syncthreads();

    const int w = tid >> 5, l = tid & 31;
    const int wm = w & 3, wn = w >> 2;
    const int mi = l >> 3, r = l & 7;
    const int k_off = (mi & 1) * 8 + r;
    const int n_off = (mi >> 1) * 8;
    const unsigned mask = ((unsigned)k_off & 7u) << 4;
    const uint32_t xrow = sb + (unsigned)k_off * 256u;

    float d[2][8][4];
#pragma unroll
    for (int i = 0; i < 2; i++)
#pragma unroll
        for (int j = 0; j < 8; j++)
#pragma unroll
            for (int e = 0; e < 4; e++) d[i][j][e] = 0.f;

#pragma unroll
    for (int ks = 0; ks < 8; ks++) {
        uint4 Ah[2];
#pragma unroll
        for (int i = 0; i < 2; i++)
            Ah[i] = Wp[((wm * 2 + i) * 8 + ks) * 32 + l];
        unsigned bh[8][2];
#pragma unroll
        for (int jp = 0; jp < 4; jp++) {
            unsigned col = (unsigned)(wn * 64 + jp * 16 + n_off);
            unsigned r0, r1, r2, r3;
            LDMX4T(r0, r1, r2, r3, xrow + (unsigned)ks * 4096u + ((col * 2u) ^ mask));
            bh[2 * jp][0] = r0; bh[2 * jp][1] = r1;
            bh[2 * jp + 1][0] = r2; bh[2 * jp + 1][1] = r3;
        }
#pragma unroll
        for (int i = 0; i < 2; i++)
#pragma unroll
            for (int j = 0; j < 8; j++)
                MMA_F16(d[i][j], Ah[i], bh[j]);
    }

    float scl = 1.f;
    if (OUTMODE == 2) { if (addScaleP) scl = __ldg(addScaleP); }
    float* Yb = Y + (size_t)b * 128 * S;
    const float* Ab = (OUTMODE == 2) ? (addp + (size_t)b * 128 * S) : nullptr;

#pragma unroll
    for (int i = 0; i < 2; i++) {
        int o0 = wm * 32 + i * 16 + (l >> 2);
        float b0v = __ldg(bias + o0);
        float b1v = __ldg(bias + o0 + 8);
#pragma unroll
        for (int j = 0; j < 8; j++) {
            int ml = wn * 64 + j * 8 + (l & 3) * 2;
            int m = m0 + ml;
            size_t p0 = (size_t)o0 * S + m;
            size_t p1 = (size_t)(o0 + 8) * S + m;
            float y0 = d[i][j][0] + b0v, y1 = d[i][j][1] + b0v;
            float y2 = d[i][j][2] + b1v, y3 = d[i][j][3] + b1v;
            if (OUTMODE == 2) {
                float2 a0 = *(const float2*)(Ab + p0);
                float2 a1 = *(const float2*)(Ab + p1);
                y0 += scl * a0.x; y1 += scl * a0.y;
                y2 += scl * a1.x; y3 += scl * a1.y;
            }
            *(float2*)(Yb + p0) = make_float2(y0, y1);
            *(float2*)(Yb + p1) = make_float2(y2, y3);
        }
    }
}

// ---------------- fused per-(b,t) cross attention (fp32 SIMT) ---------------
__global__ void __launch_bounds__(256) attn_k(
    const float* __restrict__ Q, const float* __restrict__ Kb,
    const float* __restrict__ Vb, uint4* __restrict__ Att16,
    const float* __restrict__ basis,
    const float* __restrict__ sscaleP, const float* __restrict__ pscaleP)
{
    extern __shared__ float sm[];
    float* Ks = sm;                  // [128][68]
    float* Qs = Ks + 128 * 68;       // [128][68]
    float* Vs = Qs + 128 * 68;       // [128][65]
    float* Ss = Vs + 128 * 65;       // [64][65]
    const int t = blockIdx.x, b = blockIdx.y;
    const int tid = threadIdx.x;
    const float sscale = __ldg(sscaleP), pscale = __ldg(pscaleP);

    for (int lin = tid; lin < 128 * 64; lin += 256) {
        int c = lin >> 6, kk = lin & 63;
        size_t g = ((size_t)(b * 128 + c) * 128 + t) * 64 + kk;
        Ks[c * 68 + kk] = Kb[g];
        Vs[c * 65 + kk] = Vb[g];
    }
    __syncthreads();

    const int ty = tid >> 4, tx = tid & 15;
    const int ay = tid >> 4, ax = tid & 15;

    for (int f0 = 0; f0 < 512; f0 += 64) {
        for (int lin = tid; lin < 128 * 64; lin += 256) {
            int c = lin >> 6, j = lin & 63;
            Qs[c * 68 + j] = Q[((size_t)(b * 128 + c) * 128 + t) * 512 + f0 + j];
        }
        __syncthreads();

        float acc[4][4] = {};
#pragma unroll 4
        for (int c = 0; c < 128; c++) {
            float4 af = *(const float4*)&Qs[c * 68 + ty * 4];
            float4 bf = *(const float4*)&Ks[c * 68 + tx * 4];
            float av[4] = {af.x, af.y, af.z, af.w};
            float bv[4] = {bf.x, bf.y, bf.z, bf.w};
#pragma unroll
            for (int i = 0; i < 4; i++)
#pragma unroll
                for (int j = 0; j < 4; j++)
                    acc[i][j] = fmaf(av[i], bv[j], acc[i][j]);
        }
#pragma unroll
        for (int i = 0; i < 4; i++)
#pragma unroll
            for (int j = 0; j < 4; j++) {
                int fl = ty * 4 + i, kk = tx * 4 + j;
                Ss[fl * 65 + kk] = acc[i][j] * sscale
                                 + pscale * basis[kk * 512 + f0 + fl];
            }
        __syncthreads();

        {
            int row = tid >> 2, q = tid & 3;
            float* rr = &Ss[row * 65];
            float mx = -3.4e38f;
            for (int i = q; i < 64; i += 4) mx = fmaxf(mx, rr[i]);
            mx = fmaxf(mx, __shfl_xor_sync(0xffffffffu, mx, 1));
            mx = fmaxf(mx, __shfl_xor_sync(0xffffffffu, mx, 2));
            float sum = 0.f;
            for (int i = q; i < 64; i += 4) { float e = fast_exp(rr[i] - mx); rr[i] = e; sum += e; }
            sum += __shfl_xor_sync(0xffffffffu, sum, 1);
            sum += __shfl_xor_sync(0xffffffffu, sum, 2);
            float inv = fast_rcp(sum);
            for (int i = q; i < 64; i += 4) rr[i] *= inv;
        }
        __syncthreads();

        float at[8][4] = {};
        for (int kk = 0; kk < 64; kk++) {
            float bv[4];
#pragma unroll
            for (int j = 0; j < 4; j++) bv[j] = Ss[(ax * 4 + j) * 65 + kk];
#pragma unroll
            for (int i = 0; i < 8; i++) {
                float av = Vs[(ay * 8 + i) * 65 + kk];
#pragma unroll
                for (int j = 0; j < 4; j++) at[i][j] = fmaf(av, bv[j], at[i][j]);
            }
        }
        unsigned char* tb = (unsigned char*)(Att16
            + (size_t)(b * 512 + t * 4 + (f0 >> 7)) * 2048);
        int mb = (f0 & 64) + ax * 4;
#pragma unroll
        for (int i = 0; i < 8; i++) {
            int c = ay * 8 + i;
            *(unsigned*)(tb + sw_off(c, mb))     = pack_h2(at[i][0], at[i][1]);
            *(unsigned*)(tb + sw_off(c, mb + 2)) = pack_h2(at[i][2], at[i][3]);
        }
    }
}

// ---------------- launch ----------------------------------------------------
extern "C" void kernel_launch(void* const* d_in, const int* in_sizes, int n_in,
                              void* d_out, int out_size)
{
    const float* latent     = (const float*)d_in[0];
    const float* side       = (const float*)d_in[1];
    const float* basis      = (const float*)d_in[2];
    const float* lp_gamma   = (const float*)d_in[3];
    const float* lp_w       = (const float*)d_in[4];
    const float* lp_b       = (const float*)d_in[5];
    const float* qn_gamma   = (const float*)d_in[6];
    const float* qmlp_in_w  = (const float*)d_in[7];
    const float* qmlp_in_b  = (const float*)d_in[8];
    const float* qmlp_out_w = (const float*)d_in[9];
    const float* qmlp_out_b = (const float*)d_in[10];
    const float* q_w        = (const float*)d_in[11];
    const float* q_b        = (const float*)d_in[12];
    const float* k_w        = (const float*)d_in[13];
    const float* k_b        = (const float*)d_in[14];
    const float* v_w        = (const float*)d_in[15];
    const float* v_b        = (const float*)d_in[16];
    const float* o_w        = (const float*)d_in[17];
    const float* o_b        = (const float*)d_in[18];
    const float* ffn_gamma  = (const float*)d_in[19];
    const float* ffn_in_w   = (const float*)d_in[20];
    const float* ffn_in_b   = (const float*)d_in[21];
    const float* ffn_out_w  = (const float*)d_in[22];
    const float* ffn_out_b  = (const float*)d_in[23];
    const float* score_scale      = (const float*)d_in[24];
    const float* prior_scale      = (const float*)d_in[25];
    const float* query_skip_scale = (const float*)d_in[26];
    float* out = (float*)d_out;

    float *kbuf_p, *vbuf_p, *qh_p, *q_p, *wc_p, *bc_p;
    uint4 *lat16, *A16, *att16, *wfrag;
    cudaGetSymbolAddress((void**)&kbuf_p, g_kbuf);
    cudaGetSymbolAddress((void**)&vbuf_p, g_vbuf);
    cudaGetSymbolAddress((void**)&qh_p,   g_qh);
    cudaGetSymbolAddress((void**)&q_p,    g_q);
    cudaGetSymbolAddress((void**)&lat16,  g_lat16);
    cudaGetSymbolAddress((void**)&A16,    g_A16);
    cudaGetSymbolAddress((void**)&att16,  g_att16);
    cudaGetSymbolAddress((void**)&wfrag,  g_Wp);
    cudaGetSymbolAddress((void**)&wc_p,   g_Wc);
    cudaGetSymbolAddress((void**)&bc_p,   g_bc);

    const int OFF_LP = 0, OFF_QIN = 64, OFF_QOUT = 192, OFF_Q = 256,
              OFF_K = 320, OFF_V = 384, OFF_O = 448, OFF_FIN = 512, OFF_FOUT = 640;

    // composite q-weight, then frag all 9 matrices (slot 3 = composite)
    compose_w<<<65, 256>>>(q_w, qmlp_out_w, qmlp_out_b, q_b, wc_p, bc_p);
    WPtrs wp;
    wp.p[0] = lp_w;      wp.p[1] = qmlp_in_w; wp.p[2] = qmlp_out_w;
    wp.p[3] = wc_p;      wp.p[4] = k_w;       wp.p[5] = v_w;
    wp.p[6] = o_w;       wp.p[7] = ffn_in_w;  wp.p[8] = ffn_out_w;
    prep_all<<<88, 256>>>(wp, wfrag);

    const int SMF128 = 128 * (128 + 4) * 4 + 128 * 256;   // 100352
    const int SMF256 = 128 * (64 + 4) * 4 + 128 * 128;    // 51200
    cudaFuncSetAttribute(gemm_f32in<128>, cudaFuncAttributeMaxDynamicSharedMemorySize, SMF128);
    cudaFuncSetAttribute(gemm_f32in<256>, cudaFuncAttributeMaxDynamicSharedMemorySize, SMF256);

    // latent path: rmsnorm -> lp conv -> silu -> lat16
    gemm_f32in<128><<<dim3(SL / 128, 1, 8), 256, SMF128>>>(
        wfrag + OFF_LP * 32, lp_b, latent, lp_gamma, lat16, SL);
    gemm_h16<0><<<dim3(SL / 128, 1, 8), 256>>>(
        wfrag + OFF_K * 32, k_b, lat16, SL >> 7, kbuf_p, nullptr, nullptr, SL);
    gemm_h16<0><<<dim3(SL / 128, 1, 8), 256>>>(
        wfrag + OFF_V * 32, v_b, lat16, SL >> 7, vbuf_p, nullptr, nullptr, SL);

    // side path: rmsnorm -> qmlp_in -> GLU -> A16
    gemm_f32in<256><<<dim3(SS / 64, 1, 8), 256, SMF256>>>(
        wfrag + OFF_QIN * 32, qmlp_in_b, side, qn_gamma, A16, SS);
    // q projection DIRECT from A16 via composite weight
    gemm_h16<0><<<dim3(SS / 128, 1, 8), 256>>>(
        wfrag + OFF_Q * 32, bc_p, A16, SS >> 7, q_p, nullptr, nullptr, SS);
    // qmlp_out: A16 -> qh fp32 (skip path only)
    gemm_h16<0><<<dim3(SS / 128, 1, 8), 256>>>(
        wfrag + OFF_QOUT * 32, qmlp_out_b, A16, SS >> 7, qh_p, nullptr, nullptr, SS);

    // fused attention -> att16
    cudaFuncSetAttribute(attn_k, cudaFuncAttributeMaxDynamicSharedMemorySize, 119552);
    attn_k<<<dim3(128, 8), 256, 119552>>>(q_p, kbuf_p, vbuf_p, att16, basis,
                                          score_scale, prior_scale);

    // o projection + query skip -> hidden (d_out)
    gemm_h16<2><<<dim3(SS / 128, 1, 8), 256>>>(
        wfrag + OFF_O * 32, o_b, att16, SS >> 7, out,
        qh_p, query_skip_scale, SS);

    // ffn: rmsnorm -> ffn_in -> GLU -> A16
    gemm_f32in<256><<<dim3(SS / 64, 1, 8), 256, SMF256>>>(
        wfrag + OFF_FIN * 32, ffn_in_b, out, ffn_gamma, A16, SS);
    // ffn_out + residual -> hidden (d_out)
    gemm_h16<2><<<dim3(SS / 128, 1, 8), 256>>>(
        wfrag + OFF_FOUT * 32, ffn_out_b, A16, SS >> 7, out,
        out, nullptr, SS);
}